// round 12
// baseline (speedup 1.0000x reference)
#include <cuda_runtime.h>
#include <cuda_bf16.h>
#include <cstdint>
#include <math.h>

#define NROWS 4096
#define DIM   512
#define BMI   128                 // CTA tile rows (i)
#define BNJ   64                  // CTA tile cols (j)
#define BK    64                  // bf16 elements per k-iteration (128 B/row)
#define NTI   (NROWS / BMI)       // 32
#define NITER (DIM / BK)          // 8
#define SPAD  72                  // smem row stride in bf16 (64 + 8 pad)
#define ASTGE (BMI * SPAD)        // 9216 bf16 per A stage
#define BSTGE (BNJ * SPAD)        // 4608 bf16 per B stage

// dynamic smem (bf16): As[2][128][72] | Bs[2][64][72] | sis[128]f32 | sjs[64]f32
#define SMEM_BYTES ((2 * ASTGE + 2 * BSTGE) * 2 + (BMI + BNJ) * 4)

__device__ float g_sq[NROWS];
__device__ __nv_bfloat16 g_xb[NROWS * DIM];   // bf16-rounded copy of x (4 MB)

__device__ __forceinline__ uint32_t smem_u32(const void* p) {
    uint32_t a;
    asm("{ .reg .u64 t; cvta.to.shared.u64 t, %1; cvt.u32.u64 %0, t; }"
        : "=r"(a) : "l"(p));
    return a;
}

__device__ __forceinline__ void mma16816(float* d, const uint32_t* a, const uint32_t* b) {
    asm volatile(
        "mma.sync.aligned.m16n8k16.row.col.f32.bf16.bf16.f32 "
        "{%0,%1,%2,%3}, {%4,%5,%6,%7}, {%8,%9}, {%0,%1,%2,%3};"
        : "+f"(d[0]), "+f"(d[1]), "+f"(d[2]), "+f"(d[3])
        : "r"(a[0]), "r"(a[1]), "r"(a[2]), "r"(a[3]), "r"(b[0]), "r"(b[1]));
}

#define LDSM4(r0, r1, r2, r3, addr)                                             \
    asm volatile("ldmatrix.sync.aligned.m8n8.x4.shared.b16 {%0,%1,%2,%3}, [%4];"\
        : "=r"(r0), "=r"(r1), "=r"(r2), "=r"(r3) : "r"(addr))

// ---------------------------------------------------------------------------
// Kernel 1: bf16-round x into g_xb; fp32 norms of the ROUNDED data.
// ---------------------------------------------------------------------------
__global__ void prep_kernel(const float* __restrict__ x) {
    int row  = blockIdx.x * (blockDim.x >> 5) + (threadIdx.x >> 5);
    int lane = threadIdx.x & 31;
    const float4* xr = (const float4*)(x + (size_t)row * DIM);
    uint2* dr = (uint2*)(g_xb + (size_t)row * DIM);
    float s = 0.0f;
    #pragma unroll
    for (int t = 0; t < 4; t++) {
        float4 v = xr[lane + t * 32];
        __nv_bfloat162 h0 = __floats2bfloat162_rn(v.x, v.y);
        __nv_bfloat162 h1 = __floats2bfloat162_rn(v.z, v.w);
        float a0 = __bfloat162float(h0.x), a1 = __bfloat162float(h0.y);
        float a2 = __bfloat162float(h1.x), a3 = __bfloat162float(h1.y);
        s += a0 * a0 + a1 * a1 + a2 * a2 + a3 * a3;
        uint2 o;
        o.x = *(uint32_t*)&h0; o.y = *(uint32_t*)&h1;
        dr[lane + t * 32] = o;
    }
    #pragma unroll
    for (int o = 16; o > 0; o >>= 1) s += __shfl_xor_sync(0xffffffffu, s, o);
    if (lane == 0) g_sq[row] = s;
}

// ---------------------------------------------------------------------------
// Kernel 2: 128x64 CTA tile, 32x32 warp tiles, bf16 mma.sync, 4 CTAs/SM.
// Load-all-then-MMA-all per k-slice; per-warp k-slice rotation to deconvoy.
// ---------------------------------------------------------------------------
template <int CHUNKS>
__device__ __forceinline__ void stage_tile(const __nv_bfloat16* __restrict__ src0,
                                           int row0, int k0,
                                           __nv_bfloat16* dst, int tid) {
    #pragma unroll
    for (int h = 0; h < CHUNKS; h++) {
        int e   = tid + h * 256;
        int row = e >> 3;          // 8 x 16B (8 bf16) chunks per 128B row
        int seg = e & 7;
        const __nv_bfloat16* g = src0 + (size_t)(row0 + row) * DIM + k0 + seg * 8;
        uint32_t d = smem_u32(dst + row * SPAD + seg * 8);
        asm volatile("cp.async.cg.shared.global [%0], [%1], 16;"
                     :: "r"(d), "l"(g) : "memory");
    }
}

__global__ __launch_bounds__(256, 4)
void pdist_mma_kernel(float* __restrict__ out) {
    extern __shared__ __nv_bfloat16 smb[];
    __nv_bfloat16* As = smb;
    __nv_bfloat16* Bs = smb + 2 * ASTGE;
    float* sis = (float*)(smb + 2 * ASTGE + 2 * BSTGE);
    float* sjs = sis + BMI;

    const int tid  = threadIdx.x;
    const int wid  = tid >> 5;
    const int lane = tid & 31;
    const int g    = lane >> 2;        // acc row group 0..7
    const int t    = lane & 3;         // acc col group 0..3
    const int wm   = (wid & 3) * 32;   // warp m offset (0/32/64/96)
    const int wn   = (wid >> 2) * 32;  // warp n offset (0/32)
    const int krot = (wid & 1) << 1;   // k-slice rotation: deconvoy LDSM bursts

    // block -> (ti, tj): ti over 128-row bands, tj over 64-col bands,
    // tj in [0, 2*ti+2), cumulative offset = ti^2 + ti.
    int bid = blockIdx.x;
    int ti = (int)((sqrtf(4.0f * (float)bid + 1.0f) - 1.0f) * 0.5f);
    if (ti < 0) ti = 0;
    if (ti > NTI - 1) ti = NTI - 1;
    while (ti + 1 < NTI && (ti + 1) * (ti + 2) <= bid) ti++;
    while (ti > 0 && ti * (ti + 1) > bid) ti--;
    int tj = bid - ti * (ti + 1);
    const int i0 = ti * BMI, j0 = tj * BNJ;

    if (tid < BMI) sis[tid] = g_sq[i0 + tid];
    if (tid < BNJ) sjs[tid] = g_sq[j0 + tid];

    // ldmatrix lane addresses
    const uint32_t a_base = smem_u32(
        As + (wm + (((lane >> 3) & 1) << 3) + (lane & 7)) * SPAD + ((lane >> 4) << 3));
    const uint32_t b_base = smem_u32(
        Bs + (wn + ((lane >> 4) << 3) + (lane & 7)) * SPAD + (((lane >> 3) & 1) << 3));

    float acc[2][4][4];
    #pragma unroll
    for (int a = 0; a < 2; a++)
        #pragma unroll
        for (int b = 0; b < 4; b++)
            #pragma unroll
            for (int c = 0; c < 4; c++)
                acc[a][b][c] = 0.0f;

    // prologue: stage 0
    stage_tile<4>(g_xb, i0, 0, As, tid);
    stage_tile<2>(g_xb, j0, 0, Bs, tid);
    asm volatile("cp.async.commit_group;" ::: "memory");

    for (int c = 0; c < NITER; c++) {
        const int s = c & 1;
        asm volatile("cp.async.wait_group 0;" ::: "memory");
        // one barrier: orders last iter's reads of stage s^1 before the
        // prefetch writes below, and makes stage s visible to all warps.
        __syncthreads();
        if (c + 1 < NITER) {
            const int ns = s ^ 1;
            stage_tile<4>(g_xb, i0, (c + 1) * BK, As + ns * ASTGE, tid);
            stage_tile<2>(g_xb, j0, (c + 1) * BK, Bs + ns * BSTGE, tid);
            asm volatile("cp.async.commit_group;" ::: "memory");
        }

        const uint32_t ab = a_base + (uint32_t)(s * ASTGE * 2);
        const uint32_t bb = b_base + (uint32_t)(s * BSTGE * 2);
        #pragma unroll
        for (int ks = 0; ks < 4; ks++) {
            // rotate slice order per warp parity (fp32 accumulate: order-safe)
            const uint32_t ko = (uint32_t)(((ks + krot) & 3) * 32);  // +16 bf16
            uint32_t b0[4], b1[4], a0f[4], a1f[4];
            // issue ALL fragment loads first: max LDSM->MMA distance
            LDSM4(b0[0], b0[1], b0[2], b0[3], bb + ko);
            LDSM4(b1[0], b1[1], b1[2], b1[3], bb + ko + 16 * SPAD * 2);
            LDSM4(a0f[0], a0f[1], a0f[2], a0f[3], ab + ko);
            LDSM4(a1f[0], a1f[1], a1f[2], a1f[3], ab + ko + 16 * SPAD * 2);
            // 16 MMAs on 8 independent accumulator chains
            mma16816(acc[0][0], a0f, &b0[0]);
            mma16816(acc[0][1], a0f, &b0[2]);
            mma16816(acc[0][2], a0f, &b1[0]);
            mma16816(acc[0][3], a0f, &b1[2]);
            mma16816(acc[1][0], a1f, &b0[0]);
            mma16816(acc[1][1], a1f, &b0[2]);
            mma16816(acc[1][2], a1f, &b1[0]);
            mma16816(acc[1][3], a1f, &b1[2]);
        }
    }

    // epilogue: d = sqrt(max(si + sj - 2*dot, 0)) at out[i*(i-1)/2 + j], i > j
    // full tiles: j0 + 63 < i0  <=>  tj < 2*ti
    if (tj < 2 * ti) {
        #pragma unroll
        for (int mi = 0; mi < 2; mi++)
            #pragma unroll
            for (int rr = 0; rr < 2; rr++) {
                int il = wm + mi * 16 + g + rr * 8;
                int i  = i0 + il;
                float si = sis[il];
                float* orow = out + (size_t)((unsigned)i * (unsigned)(i - 1) / 2u) + j0 + wn;
                #pragma unroll
                for (int ni = 0; ni < 4; ni++)
                    #pragma unroll
                    for (int cc = 0; cc < 2; cc++) {
                        int jl = ni * 8 + 2 * t + cc;
                        float d2 = si + sjs[wn + jl] - 2.0f * acc[mi][ni][rr * 2 + cc];
                        orow[jl] = sqrtf(fmaxf(d2, 0.0f));
                    }
            }
    } else {
        #pragma unroll
        for (int mi = 0; mi < 2; mi++)
            #pragma unroll
            for (int rr = 0; rr < 2; rr++) {
                int il = wm + mi * 16 + g + rr * 8;
                int i  = i0 + il;
                float si = sis[il];
                unsigned base = (unsigned)i * (unsigned)(i - 1) / 2u;
                #pragma unroll
                for (int ni = 0; ni < 4; ni++)
                    #pragma unroll
                    for (int cc = 0; cc < 2; cc++) {
                        int jl = wn + ni * 8 + 2 * t + cc;
                        int j  = j0 + jl;
                        if (j < i) {
                            float d2 = si + sjs[jl] - 2.0f * acc[mi][ni][rr * 2 + cc];
                            out[base + (unsigned)j] = sqrtf(fmaxf(d2, 0.0f));
                        }
                    }
            }
    }
}

extern "C" void kernel_launch(void* const* d_in, const int* in_sizes, int n_in,
                              void* d_out, int out_size) {
    const float* x = (const float*)d_in[0];
    float* out = (float*)d_out;

    cudaFuncSetAttribute(pdist_mma_kernel,
                         cudaFuncAttributeMaxDynamicSharedMemorySize, SMEM_BYTES);

    prep_kernel<<<NROWS / 8, 256>>>(x);

    const int nblocks = NTI * NTI + NTI;   // sum over ti of (2*ti + 2) = 1056
    pdist_mma_kernel<<<nblocks, 256, SMEM_BYTES>>>(out);
}